// round 5
// baseline (speedup 1.0000x reference)
#include <cuda_runtime.h>

// MultiLayerRNNModel: 2-layer tanh RNN, T=2048, B=4096, I=3, H=5
// out = concat(out[T,B,H], h_n[2,B,H])
//
// R5: thread-per-batch (zero inter-lane communication) + packed f32x2 FMA.
// Each thread computes all 5 units of both layers for one batch; the
// recurrence chain contains only FMA+MUFU (no SHFL/STS/LDS/BAR -> no MIO
// round trip). Output units are packed in pairs (0,1),(2,3),(4,dup) into
// 64-bit f32x2 registers; fma.rn.f32x2 halves FMA issue/throughput cost.
// 128 blocks x 32 threads = 4096 threads, one warp per SM.

#define T_LEN   2048
#define B_SZ    4096
#define XSTRIDE (B_SZ * 3)
#define OSTRIDE (B_SZ * 5)
#define PF      4

typedef unsigned long long ull;

__device__ __forceinline__ float tanh_fast(float v) {
    float y;
    asm("tanh.approx.f32 %0, %1;" : "=f"(y) : "f"(v));
    return y;
}
__device__ __forceinline__ ull pk2(float lo, float hi) {
    ull r;
    asm("mov.b64 %0, {%1, %2};" : "=l"(r) : "f"(lo), "f"(hi));
    return r;
}
__device__ __forceinline__ ull splat2(float v) { return pk2(v, v); }
__device__ __forceinline__ ull fma2(ull a, ull b, ull c) {
    ull d;
    asm("fma.rn.f32x2 %0, %1, %2, %3;" : "=l"(d) : "l"(a), "l"(b), "l"(c));
    return d;
}
__device__ __forceinline__ float lo2(ull v) {
    float a;
    asm("{ .reg .b32 hi; mov.b64 {%0, hi}, %1; }" : "=f"(a) : "l"(v));
    return a;
}
__device__ __forceinline__ float hi2(ull v) {
    float a;
    asm("{ .reg .b32 lo; mov.b64 {lo, %0}, %1; }" : "=f"(a) : "l"(v));
    return a;
}

__global__ __launch_bounds__(32, 1)
void rnn2_kernel(const float* __restrict__ x,
                 const float* __restrict__ hx,
                 const float* __restrict__ w_ih0,
                 const float* __restrict__ w_hh0,
                 const float* __restrict__ b_ih0,
                 const float* __restrict__ b_hh0,
                 const float* __restrict__ w_ih1,
                 const float* __restrict__ w_hh1,
                 const float* __restrict__ b_ih1,
                 const float* __restrict__ b_hh1,
                 float* __restrict__ out)
{
    const int b = blockIdx.x * 32 + threadIdx.x;   // exact: 128*32 = 4096

    // ---- packed weights: unit pairs (0,1),(2,3),(4,4-dup) ----
    ull WI0[3][3], WH0[3][5], WI1[3][5], WH1[3][5], B0[3], B1[3];
    #pragma unroll
    for (int v = 0; v < 3; v++) {
        const int j0 = 2 * v;
        const int j1 = (2 * v + 1 < 5) ? 2 * v + 1 : 4;
        #pragma unroll
        for (int i = 0; i < 3; i++)
            WI0[v][i] = pk2(w_ih0[j0 * 3 + i], w_ih0[j1 * 3 + i]);
        #pragma unroll
        for (int k = 0; k < 5; k++) {
            WH0[v][k] = pk2(w_hh0[j0 * 5 + k], w_hh0[j1 * 5 + k]);
            WI1[v][k] = pk2(w_ih1[j0 * 5 + k], w_ih1[j1 * 5 + k]);
            WH1[v][k] = pk2(w_hh1[j0 * 5 + k], w_hh1[j1 * 5 + k]);
        }
        B0[v] = pk2(b_ih0[j0] + b_hh0[j0], b_ih0[j1] + b_hh0[j1]);
        B1[v] = pk2(b_ih1[j0] + b_hh1[j0], b_ih1[j1] + b_hh1[j1]);
    }

    // ---- state kept as pre-splatted f32x2 (both halves identical) ----
    ull H0[5], H1[5];
    #pragma unroll
    for (int k = 0; k < 5; k++) {
        H0[k] = splat2(hx[b * 5 + k]);
        H1[k] = splat2(hx[B_SZ * 5 + b * 5 + k]);
    }

    const float* xb = x + b * 3;
    float*       op = out + b * 5;

    // x prefetch queue, PF steps deep (coalesced: 3 floats/thread)
    float xq[PF][3];
    #pragma unroll
    for (int p = 0; p < PF; p++) {
        const float* xp = xb + p * XSTRIDE;
        xq[p][0] = xp[0]; xq[p][1] = xp[1]; xq[p][2] = xp[2];
    }

// One full step (both layers, no communication). P == t & (PF-1), literal.
#define STEP(t, P) {                                                          \
    const float x0 = xq[P][0], x1 = xq[P][1], x2 = xq[P][2];                  \
    if ((t) + PF < T_LEN) {                                                   \
        const float* xp = xb + ((t) + PF) * XSTRIDE;                          \
        xq[P][0] = xp[0]; xq[P][1] = xp[1]; xq[P][2] = xp[2];                 \
    }                                                                         \
    const ull X0 = splat2(x0), X1 = splat2(x1), X2 = splat2(x2);              \
    /* layer 0: s = W_ih0 x + b0 + W_hh0 h0   (3 independent v-chains) */     \
    ull A[3];                                                                 \
    _Pragma("unroll")                                                         \
    for (int v = 0; v < 3; v++) {                                             \
        ull a = fma2(WI0[v][0], X0, B0[v]);                                   \
        a = fma2(WI0[v][1], X1, a);                                           \
        a = fma2(WI0[v][2], X2, a);                                           \
        a = fma2(WH0[v][0], H0[0], a);                                        \
        a = fma2(WH0[v][1], H0[1], a);                                        \
        a = fma2(WH0[v][2], H0[2], a);                                        \
        a = fma2(WH0[v][3], H0[3], a);                                        \
        A[v] = fma2(WH0[v][4], H0[4], a);                                     \
    }                                                                         \
    const float n0 = tanh_fast(lo2(A[0]));                                    \
    const float n1 = tanh_fast(hi2(A[0]));                                    \
    const float n2 = tanh_fast(lo2(A[1]));                                    \
    const float n3 = tanh_fast(hi2(A[1]));                                    \
    const float n4 = tanh_fast(lo2(A[2]));                                    \
    const ull N0 = splat2(n0), N1 = splat2(n1), N2 = splat2(n2),              \
              N3 = splat2(n3), N4 = splat2(n4);                               \
    /* layer 1: u = W_ih1 h0new + b1 + W_hh1 h1old (h1 terms first: off-chain) */ \
    ull C[3];                                                                 \
    _Pragma("unroll")                                                         \
    for (int v = 0; v < 3; v++) {                                             \
        ull c = fma2(WH1[v][0], H1[0], B1[v]);                                \
        c = fma2(WH1[v][1], H1[1], c);                                        \
        c = fma2(WH1[v][2], H1[2], c);                                        \
        c = fma2(WH1[v][3], H1[3], c);                                        \
        c = fma2(WH1[v][4], H1[4], c);                                        \
        c = fma2(WI1[v][0], N0, c);                                           \
        c = fma2(WI1[v][1], N1, c);                                           \
        c = fma2(WI1[v][2], N2, c);                                           \
        c = fma2(WI1[v][3], N3, c);                                           \
        C[v] = fma2(WI1[v][4], N4, c);                                        \
    }                                                                         \
    const float m0 = tanh_fast(lo2(C[0]));                                    \
    const float m1 = tanh_fast(hi2(C[0]));                                    \
    const float m2 = tanh_fast(lo2(C[1]));                                    \
    const float m3 = tanh_fast(hi2(C[1]));                                    \
    const float m4 = tanh_fast(lo2(C[2]));                                    \
    H0[0] = N0; H0[1] = N1; H0[2] = N2; H0[3] = N3; H0[4] = N4;               \
    H1[0] = splat2(m0); H1[1] = splat2(m1); H1[2] = splat2(m2);               \
    H1[3] = splat2(m3); H1[4] = splat2(m4);                                   \
    float* o = op + (t) * OSTRIDE;                                            \
    o[0] = m0; o[1] = m1; o[2] = m2; o[3] = m3; o[4] = m4;                    \
}

    for (int t0 = 0; t0 < T_LEN; t0 += PF) {
        STEP(t0 + 0, 0);
        STEP(t0 + 1, 1);
        STEP(t0 + 2, 2);
        STEP(t0 + 3, 3);
    }
#undef STEP

    // ---- h_n[2, B, H] ----
    float* hn = op + (size_t)T_LEN * OSTRIDE;
    #pragma unroll
    for (int k = 0; k < 5; k++) {
        hn[k]           = lo2(H0[k]);
        hn[OSTRIDE + k] = lo2(H1[k]);
    }
}

extern "C" void kernel_launch(void* const* d_in, const int* in_sizes, int n_in,
                              void* d_out, int out_size)
{
    const float* x     = (const float*)d_in[0];
    const float* hx    = (const float*)d_in[1];
    const float* w_ih0 = (const float*)d_in[2];
    const float* w_hh0 = (const float*)d_in[3];
    const float* b_ih0 = (const float*)d_in[4];
    const float* b_hh0 = (const float*)d_in[5];
    const float* w_ih1 = (const float*)d_in[6];
    const float* w_hh1 = (const float*)d_in[7];
    const float* b_ih1 = (const float*)d_in[8];
    const float* b_hh1 = (const float*)d_in[9];
    float* out = (float*)d_out;

    // 128 blocks x 32 threads: one warp per block, ~1 block per SM.
    rnn2_kernel<<<128, 32>>>(x, hx, w_ih0, w_hh0, b_ih0, b_hh0,
                             w_ih1, w_hh1, b_ih1, b_hh1, out);
}